// round 2
// baseline (speedup 1.0000x reference)
#include <cuda_runtime.h>
#include <float.h>

// fm [B=4, C=256, H=50, W=50] f32, rois [R=300,5] f32 -> out [R,256,7,7] f32.
#define PH 7
#define PW 7
#define C_ 256
#define H_ 50
#define W_ 50
#define MAX_R 512

#define NC 16            // channels per block
#define TPB 128          // 4 warps
#define ROWS_MAX 8       // max strip height: ceil(49/7)+1 = 8
#define WPITCH 52        // row pitch in smem (floats)
#define CH_STRIDE 420    // 8*52 + 4 pad -> shifts banks by 4 per channel

struct RoiInfo {
    int base;               // b * C*H*W
    int x0;                 // left edge (clamped)
    int w;                  // roi width  (1..49)
    unsigned char hs[PH];   // absolute strip start row per ph
    unsigned char sh[PH];   // strip height per ph (1..8)
    unsigned char wsr[PW];  // bin start, relative to x0
    unsigned char bw[PW];   // bin width
};

__device__ RoiInfo g_roi[MAX_R];

// All rounding / clamping / bin-edge math done once per ROI.
// jnp.round == round-half-to-even == rintf (default RN mode).
__global__ void roi_prep_kernel(const float* __restrict__ rois, int R) {
    int r = blockIdx.x * blockDim.x + threadIdx.x;
    if (r >= R) return;
    const float* p = rois + r * 5;
    int b  = (int)p[4];                               // float truncation
    int x0 = min(max((int)rintf(p[0]), 0), W_ - 1);
    int x1 = min(max((int)rintf(p[2]), 0), W_ - 1);
    int y0 = min(max((int)rintf(p[1]), 0), H_ - 1);
    int y1 = min(max((int)rintf(p[3]), 0), H_ - 1);
    x1 = max(x1, x0 + 1);   // can reach 50; reads stay <= 49
    y1 = max(y1, y0 + 1);
    int w = x1 - x0, h = y1 - y0;

    RoiInfo info;
    info.base = b * (C_ * H_ * W_);
    info.x0 = x0;
    info.w  = w;
    #pragma unroll
    for (int i = 0; i < PH; ++i) {
        int s = y0 + (i * h) / PH;
        int e = y0 + ((i + 1) * h + PH - 1) / PH;     // ceil
        info.hs[i] = (unsigned char)s;
        info.sh[i] = (unsigned char)(e - s);
    }
    #pragma unroll
    for (int i = 0; i < PW; ++i) {
        int s = (i * w) / PW;
        int e = ((i + 1) * w + PW - 1) / PW;
        info.wsr[i] = (unsigned char)s;
        info.bw[i]  = (unsigned char)(e - s);
    }
    g_roi[r] = info;
}

// Block = (roi r, 16-channel chunk). For each ph strip: stage rows into smem
// coalesced (warp per channel), then 112 threads compute 16ch x 7pw maxes.
__global__ __launch_bounds__(TPB) void roi_pool_kernel(
        const float* __restrict__ fm, float* __restrict__ out) {
    __shared__ float tile[NC * CH_STRIDE];
    __shared__ RoiInfo info;

    const int r     = blockIdx.y;
    const int cbase = blockIdx.x * NC;
    const int tid   = threadIdx.x;
    const int lane  = tid & 31;
    const int wid   = tid >> 5;            // 0..3

    if (tid == 0) info = g_roi[r];
    __syncthreads();

    const int   x0 = info.x0;
    const int   w  = info.w;
    const float* fbase = fm + info.base + (size_t)cbase * (H_ * W_);

    // compute-phase role (fixed across ph iterations)
    const int ch_c = tid / PW;             // 0..15 (tid<112)
    const int pw_c = tid % PW;
    const int xs   = info.wsr[pw_c];
    const int xe   = xs + info.bw[pw_c];

    for (int ph = 0; ph < PH; ++ph) {
        const int hs = info.hs[ph];
        const int sh = info.sh[ph];

        // ---- stage strip: warp per channel, lanes along x (coalesced) ----
        for (int ch = wid; ch < NC; ch += 4) {
            const float* src = fbase + ch * (H_ * W_) + hs * W_ + x0;
            float* dst = tile + ch * CH_STRIDE;
            for (int y = 0; y < sh; ++y) {
                for (int x = lane; x < w; x += 32)
                    dst[y * WPITCH + x] = __ldg(src + y * W_ + x);
            }
        }
        __syncthreads();

        // ---- pool 16 channels x 7 w-bins from smem ----
        if (tid < NC * PW) {
            const float* t = tile + ch_c * CH_STRIDE;
            float m = -FLT_MAX;
            for (int y = 0; y < sh; ++y) {
                const float* row = t + y * WPITCH;
                for (int x = xs; x < xe; ++x)
                    m = fmaxf(m, row[x]);
            }
            out[(((size_t)r * C_ + cbase + ch_c) * PH + ph) * PW + pw_c] = m;
        }
        __syncthreads();   // protect tile before next strip overwrites it
    }
}

extern "C" void kernel_launch(void* const* d_in, const int* in_sizes, int n_in,
                              void* d_out, int out_size) {
    const float* fm   = (const float*)d_in[0];
    const float* rois = (const float*)d_in[1];
    float* out = (float*)d_out;

    int R = in_sizes[1] / 5;

    roi_prep_kernel<<<(R + 127) / 128, 128>>>(rois, R);

    dim3 grid(C_ / NC, R);
    roi_pool_kernel<<<grid, TPB>>>(fm, out);
}

// round 3
// speedup vs baseline: 3.9008x; 3.9008x over previous
#include <cuda_runtime.h>
#include <float.h>

// fm [B=4, C=256, H=50, W=50] f32, rois [R=300,5] f32 -> out [R,256,7,7] f32.
#define PH 7
#define PW 7
#define C_ 256
#define H_ 50
#define W_ 50
#define HW (H_ * W_)
#define MAX_R 512
#define NCH 8                       // channels per thread
#define BINS (PH * PW)              // 49
#define CG (C_ / NCH)               // 32 channel-groups
#define TPR (BINS * CG)             // 1568 threads per roi

__device__ int    g_base[MAX_R];           // b * C*H*W
__device__ uchar2 g_h[MAX_R][PH];          // {row start (abs), strip height}
__device__ uchar2 g_w[MAX_R][PW];          // {col start (abs), bin width}

// All rounding / clamping / bin-edge math once per ROI.
// jnp.round == round-half-to-even == rintf (default RN mode).
__global__ void roi_prep_kernel(const float* __restrict__ rois, int R) {
    int r = blockIdx.x * blockDim.x + threadIdx.x;
    if (r >= R) return;
    const float* p = rois + r * 5;
    int b  = (int)p[4];                               // float truncation
    int x0 = min(max((int)rintf(p[0]), 0), W_ - 1);
    int x1 = min(max((int)rintf(p[2]), 0), W_ - 1);
    int y0 = min(max((int)rintf(p[1]), 0), H_ - 1);
    int y1 = min(max((int)rintf(p[3]), 0), H_ - 1);
    x1 = max(x1, x0 + 1);   // logical edge may reach 50; reads stay <= 49
    y1 = max(y1, y0 + 1);
    int w = x1 - x0, h = y1 - y0;

    g_base[r] = b * (C_ * HW);
    #pragma unroll
    for (int i = 0; i < PH; ++i) {
        int s = y0 + (i * h) / PH;
        int e = y0 + ((i + 1) * h + PH - 1) / PH;     // ceil
        g_h[r][i] = make_uchar2((unsigned char)s, (unsigned char)(e - s));
    }
    #pragma unroll
    for (int i = 0; i < PW; ++i) {
        int s = x0 + (i * w) / PW;
        int e = x0 + ((i + 1) * w + PW - 1) / PW;
        g_w[r][i] = make_uchar2((unsigned char)s, (unsigned char)(e - s));
    }
}

// Thread = (roi, 8-channel group, bin). One 2D bin loop, 8 planes maxed
// simultaneously via immediate-offset LDGs (stride 2500 floats per plane).
__global__ __launch_bounds__(256) void roi_pool_kernel(
        const float* __restrict__ fm, float* __restrict__ out) {
    const int r = blockIdx.y;
    int t = blockIdx.x * 256 + threadIdx.x;
    if (t >= TPR) return;

    const int bin = t % BINS;        // 0..48  (ph*7+pw)
    const int cg  = t / BINS;        // 0..31
    const int ph  = bin / PW;
    const int pw  = bin % PW;

    const uchar2 hi = g_h[r][ph];
    const uchar2 wi = g_w[r][pw];
    const int hs = hi.x, sh = hi.y;
    const int ws = wi.x, bw = wi.y;

    const float* base = fm + g_base[r] + (size_t)cg * (NCH * HW);

    float m0 = -FLT_MAX, m1 = -FLT_MAX, m2 = -FLT_MAX, m3 = -FLT_MAX;
    float m4 = -FLT_MAX, m5 = -FLT_MAX, m6 = -FLT_MAX, m7 = -FLT_MAX;

    for (int y = hs; y < hs + sh; ++y) {
        const float* p = base + y * W_ + ws;
        for (int x = 0; x < bw; ++x) {
            m0 = fmaxf(m0, __ldg(p + x));
            m1 = fmaxf(m1, __ldg(p + x + 1 * HW));
            m2 = fmaxf(m2, __ldg(p + x + 2 * HW));
            m3 = fmaxf(m3, __ldg(p + x + 3 * HW));
            m4 = fmaxf(m4, __ldg(p + x + 4 * HW));
            m5 = fmaxf(m5, __ldg(p + x + 5 * HW));
            m6 = fmaxf(m6, __ldg(p + x + 6 * HW));
            m7 = fmaxf(m7, __ldg(p + x + 7 * HW));
        }
    }

    float* o = out + ((size_t)r * C_ + cg * NCH) * BINS + bin;
    o[0 * BINS] = m0;  o[1 * BINS] = m1;  o[2 * BINS] = m2;  o[3 * BINS] = m3;
    o[4 * BINS] = m4;  o[5 * BINS] = m5;  o[6 * BINS] = m6;  o[7 * BINS] = m7;
}

extern "C" void kernel_launch(void* const* d_in, const int* in_sizes, int n_in,
                              void* d_out, int out_size) {
    const float* fm   = (const float*)d_in[0];
    const float* rois = (const float*)d_in[1];
    float* out = (float*)d_out;

    int R = in_sizes[1] / 5;

    roi_prep_kernel<<<(R + 127) / 128, 128>>>(rois, R);

    dim3 grid((TPR + 255) / 256, R);   // 7 x 300
    roi_pool_kernel<<<grid, 256>>>(fm, out);
}

// round 4
// speedup vs baseline: 4.4615x; 1.1437x over previous
#include <cuda_runtime.h>
#include <float.h>

// fm [B=4, C=256, H=50, W=50] f32, rois [R=300,5] f32 -> out [R,256,7,7] f32.
#define PH 7
#define PW 7
#define C_ 256
#define H_ 50
#define W_ 50
#define HW (H_ * W_)
#define MAX_R 512
#define NCH 4                        // channels per thread
#define BINS (PH * PW)               // 49
#define CG (C_ / NCH)                // 64 channel-groups
#define TPR (BINS * CG)              // 3136 threads per roi
#define TPB 224                      // 3136 = 14 * 224, no tail

__device__ int    g_base[MAX_R];     // b * C*H*W
__device__ uchar2 g_hh[MAX_R][PH];   // {row start (abs), strip height}
__device__ uchar2 g_ww[MAX_R][PW];   // {col start (abs), bin width}

// All rounding / clamping / bin-edge math once per ROI.
// jnp.round == round-half-to-even == rintf (default RN mode).
__global__ void roi_prep_kernel(const float* __restrict__ rois, int R) {
    int r = blockIdx.x * blockDim.x + threadIdx.x;
    if (r >= R) return;
    const float* p = rois + r * 5;
    int b  = (int)p[4];                               // float truncation
    int x0 = min(max((int)rintf(p[0]), 0), W_ - 1);
    int x1 = min(max((int)rintf(p[2]), 0), W_ - 1);
    int y0 = min(max((int)rintf(p[1]), 0), H_ - 1);
    int y1 = min(max((int)rintf(p[3]), 0), H_ - 1);
    x1 = max(x1, x0 + 1);   // logical edge may reach 50; reads stay <= 49
    y1 = max(y1, y0 + 1);
    int w = x1 - x0, h = y1 - y0;

    g_base[r] = b * (C_ * HW);
    #pragma unroll
    for (int i = 0; i < PH; ++i) {
        int s = y0 + (i * h) / PH;
        int e = y0 + ((i + 1) * h + PH - 1) / PH;     // ceil
        g_hh[r][i] = make_uchar2((unsigned char)s, (unsigned char)(e - s));
    }
    #pragma unroll
    for (int i = 0; i < PW; ++i) {
        int s = x0 + (i * w) / PW;
        int e = x0 + ((i + 1) * w + PW - 1) / PW;
        g_ww[r][i] = make_uchar2((unsigned char)s, (unsigned char)(e - s));
    }
}

// Thread = (roi, 4-channel group, bin). Bin row read as aligned float2s
// (edges masked); 4 planes maxed via immediate-offset LDGs.
__global__ __launch_bounds__(TPB) void roi_pool_kernel(
        const float* __restrict__ fm, float* __restrict__ out) {
    const int r = blockIdx.y;
    const int t = blockIdx.x * TPB + threadIdx.x;   // 0..3135, exact

    const int bin = t % BINS;        // ph*7+pw
    const int cg  = t / BINS;        // 0..63
    const int ph  = bin / PW;
    const int pw  = bin % PW;

    const uchar2 hi = g_hh[r][ph];
    const uchar2 wi = g_ww[r][pw];
    const int hs = hi.x, sh = hi.y;
    const int ws = wi.x;
    const int we = ws + wi.y;        // exclusive end, <= 50
    const int xs2 = ws & ~1;         // align down to even -> 8B-aligned float2
    const int nf2 = (we - xs2 + 1) >> 1;   // <= 5

    const float* base = fm + g_base[r] + (size_t)cg * (NCH * HW);

    float m0 = -FLT_MAX, m1 = -FLT_MAX, m2 = -FLT_MAX, m3 = -FLT_MAX;

    for (int y = hs; y < hs + sh; ++y) {
        const float* row = base + y * W_;
        for (int i = 0; i < nf2; ++i) {
            const int px = xs2 + 2 * i;
            const float* q = row + px;
            float2 a0 = __ldg((const float2*)(q));
            float2 a1 = __ldg((const float2*)(q + 1 * HW));
            float2 a2 = __ldg((const float2*)(q + 2 * HW));
            float2 a3 = __ldg((const float2*)(q + 3 * HW));
            // element validity: lo fails only when px < ws (first i, ws odd);
            // hi fails only when px+1 >= we (last i).
            const bool vlo = (px >= ws);
            const bool vhi = (px + 1 < we);
            m0 = fmaxf(m0, vlo ? a0.x : -FLT_MAX);
            m1 = fmaxf(m1, vlo ? a1.x : -FLT_MAX);
            m2 = fmaxf(m2, vlo ? a2.x : -FLT_MAX);
            m3 = fmaxf(m3, vlo ? a3.x : -FLT_MAX);
            m0 = fmaxf(m0, vhi ? a0.y : -FLT_MAX);
            m1 = fmaxf(m1, vhi ? a1.y : -FLT_MAX);
            m2 = fmaxf(m2, vhi ? a2.y : -FLT_MAX);
            m3 = fmaxf(m3, vhi ? a3.y : -FLT_MAX);
        }
    }

    float* o = out + ((size_t)r * C_ + cg * NCH) * BINS + bin;
    o[0 * BINS] = m0;
    o[1 * BINS] = m1;
    o[2 * BINS] = m2;
    o[3 * BINS] = m3;
}

extern "C" void kernel_launch(void* const* d_in, const int* in_sizes, int n_in,
                              void* d_out, int out_size) {
    const float* fm   = (const float*)d_in[0];
    const float* rois = (const float*)d_in[1];
    float* out = (float*)d_out;

    int R = in_sizes[1] / 5;

    roi_prep_kernel<<<(R + 127) / 128, 128>>>(rois, R);

    dim3 grid(TPR / TPB, R);         // 14 x 300
    roi_pool_kernel<<<grid, TPB>>>(fm, out);
}